// round 2
// baseline (speedup 1.0000x reference)
#include <cuda_runtime.h>
#include <math.h>

#define EDIM 256
#define TM 64
#define XLD 260   // padded row stride (multiple of 4 for aligned float4)

// ---------------- device-global scratch (allocation-free workaround) --------
__device__ float g_enc1[EDIM*EDIM], g_enc2[EDIM*EDIM];
__device__ float g_aff_a[EDIM*EDIM], g_aff_v[EDIM*EDIM];
__device__ float g_A1[EDIM*EDIM],  g_A2[EDIM*EDIM];
__device__ float g_wca_t[EDIM*EDIM], g_wcv_t[EDIM*EDIM];
__device__ float g_wha_t[EDIM*EDIM], g_whv_t[EDIM*EDIM];
__device__ float g_fc1a_t[EDIM*EDIM], g_fc1b_t[EDIM*EDIM];

// ---------------- prep: transpose weights to k-major ------------------------
__global__ void transpose_prep(const float* __restrict__ wca,
                               const float* __restrict__ wcv,
                               const float* __restrict__ wha,
                               const float* __restrict__ whv,
                               const float* __restrict__ fc1) {
    __shared__ float t[32][33];
    int z = blockIdx.z;
    const float* src; int ld; float* dst;
    switch (z) {
        case 0: src = wca;       ld = 256; dst = g_wca_t;  break;
        case 1: src = wcv;       ld = 256; dst = g_wcv_t;  break;
        case 2: src = wha;       ld = 256; dst = g_wha_t;  break;
        case 3: src = whv;       ld = 256; dst = g_whv_t;  break;
        case 4: src = fc1;       ld = 512; dst = g_fc1a_t; break;
        default: src = fc1 + 256; ld = 512; dst = g_fc1b_t; break;
    }
    int j = blockIdx.y * 32 + threadIdx.y;   // source row
    int k = blockIdx.x * 32 + threadIdx.x;   // source col
    t[threadIdx.y][threadIdx.x] = src[j * ld + k];
    __syncthreads();
    int ko = blockIdx.x * 32 + threadIdx.y;
    int jo = blockIdx.y * 32 + threadIdx.x;
    dst[ko * 256 + jo] = t[threadIdx.x][threadIdx.y];
}

// ---------------- generic small GEMM: C = A @ B^T (+bias) -------------------
__global__ void gemm_nt(const float* __restrict__ A, const float* __restrict__ B,
                        const float* __restrict__ bias, float* __restrict__ C,
                        int M, int N, int K) {
    __shared__ float As[16][17], Bs[16][17];
    int tx = threadIdx.x, ty = threadIdx.y;
    int row = blockIdx.y * 16 + ty;
    int col = blockIdx.x * 16 + tx;
    float acc = 0.f;
    for (int k0 = 0; k0 < K; k0 += 16) {
        As[ty][tx] = A[row * K + k0 + tx];
        Bs[ty][tx] = B[(blockIdx.x * 16 + ty) * K + k0 + tx];
        __syncthreads();
#pragma unroll
        for (int kk = 0; kk < 16; kk++) acc = fmaf(As[ty][kk], Bs[tx][kk], acc);
        __syncthreads();
    }
    C[row * N + col] = acc + (bias ? bias[col] : 0.f);
}

// ---------------- fused per-batch row-chain kernel ---------------------------
#define F4GET(v, kk) ((kk) == 0 ? (v).x : (kk) == 1 ? (v).y : (kk) == 2 ? (v).z : (v).w)

// Y[i][j] = epi( sum_k X[i][k]*Wt[k][j] + gAdd[i*256+j] ), X,dst in smem [TM][XLD]
// In-place (dst == X) is safe: all X reads finish before the barrier preceding
// the epilogue, and each row is read/written only by its own ty-group columns.
__device__ __forceinline__ void tile_gemm(const float* __restrict__ X,
                                          const float* __restrict__ Wt,
                                          float* __restrict__ sW,
                                          float* __restrict__ dst,
                                          const float* __restrict__ gAdd,
                                          bool do_relu, int tid) {
    const int ty = tid >> 4, tx = tid & 15;
    float acc[4][16];
#pragma unroll
    for (int r = 0; r < 4; r++)
#pragma unroll
        for (int c = 0; c < 16; c++) acc[r][c] = 0.f;

    // stage chunk 0 (8 k-rows of Wt = 2048 contiguous floats)
    {
        const float4* src = (const float4*)Wt;
        float4 v0 = src[tid * 2], v1 = src[tid * 2 + 1];
        *(float4*)(sW + tid * 8) = v0;
        *(float4*)(sW + tid * 8 + 4) = v1;
    }
    __syncthreads();

    int buf = 0;
    for (int k0 = 0; k0 < 256; k0 += 8) {
        const bool more = (k0 + 8) < 256;
        float4 n0, n1;
        if (more) {
            const float4* src = (const float4*)(Wt + (k0 + 8) * 256);
            n0 = src[tid * 2]; n1 = src[tid * 2 + 1];
        }
        const float* Wb = sW + buf * 4096;
#pragma unroll
        for (int g = 0; g < 2; g++) {
            float4 xv[4];
#pragma unroll
            for (int r = 0; r < 4; r++)
                xv[r] = *(const float4*)(X + (ty * 4 + r) * XLD + k0 + g * 4);
#pragma unroll
            for (int kk = 0; kk < 4; kk++) {
                float w[16];
#pragma unroll
                for (int c = 0; c < 16; c++) w[c] = Wb[(g * 4 + kk) * 256 + c * 16 + tx];
                float xs[4];
#pragma unroll
                for (int r = 0; r < 4; r++) xs[r] = F4GET(xv[r], kk);
#pragma unroll
                for (int r = 0; r < 4; r++)
#pragma unroll
                    for (int c = 0; c < 16; c++) acc[r][c] = fmaf(xs[r], w[c], acc[r][c]);
            }
        }
        __syncthreads();
        if (more) {
            float* Wn = sW + (buf ^ 1) * 4096;
            *(float4*)(Wn + tid * 8) = n0;
            *(float4*)(Wn + tid * 8 + 4) = n1;
        }
        buf ^= 1;
        __syncthreads();
    }

    // epilogue (all reads of X are complete: barrier above)
#pragma unroll
    for (int r = 0; r < 4; r++) {
        const int i = ty * 4 + r;
#pragma unroll
        for (int c = 0; c < 16; c++) {
            const int j = c * 16 + tx;
            float v = acc[r][c] + gAdd[i * 256 + j];
            if (do_relu) v = fmaxf(v, 0.f);
            dst[i * XLD + j] = v;
        }
    }
    __syncthreads();
}

// h = relu(P@fc1a^T + Q@fc1b^T + b1); out = h . fc2 + b2
__device__ __forceinline__ void fc_final(const float* __restrict__ P,
                                         const float* __restrict__ Q,
                                         float* __restrict__ sW,
                                         const float* __restrict__ sFb,
                                         const float* __restrict__ sFc2,
                                         float fc2b0, float* __restrict__ out,
                                         int b, int r0, int tid) {
    const int ty = tid >> 4, tx = tid & 15;
    float acc[4][16];
#pragma unroll
    for (int r = 0; r < 4; r++)
#pragma unroll
        for (int c = 0; c < 16; c++) acc[r][c] = sFb[c * 16 + tx];

    const int kk0 = (tid * 16) >> 9;
    const int jj  = (tid * 16) & 511;

    // stage chunk 0: 8 k-rows of [fc1a | fc1b] = 4096 floats
    {
        const float* s = (jj < 256) ? (g_fc1a_t + kk0 * 256 + jj)
                                    : (g_fc1b_t + kk0 * 256 + (jj - 256));
        float4 m0 = *(const float4*)s, m1 = *(const float4*)(s + 4);
        float4 m2 = *(const float4*)(s + 8), m3 = *(const float4*)(s + 12);
        float* d = sW + tid * 16;
        *(float4*)d = m0; *(float4*)(d + 4) = m1;
        *(float4*)(d + 8) = m2; *(float4*)(d + 12) = m3;
    }
    __syncthreads();

    int buf = 0;
    for (int k0 = 0; k0 < 256; k0 += 8) {
        const bool more = (k0 + 8) < 256;
        float4 n0, n1, n2, n3;
        if (more) {
            const float* s = (jj < 256) ? (g_fc1a_t + (k0 + 8 + kk0) * 256 + jj)
                                        : (g_fc1b_t + (k0 + 8 + kk0) * 256 + (jj - 256));
            n0 = *(const float4*)s;       n1 = *(const float4*)(s + 4);
            n2 = *(const float4*)(s + 8); n3 = *(const float4*)(s + 12);
        }
        const float* Wb = sW + buf * 4096;
#pragma unroll
        for (int g = 0; g < 2; g++) {
            float4 av[4], bv[4];
#pragma unroll
            for (int r = 0; r < 4; r++) {
                av[r] = *(const float4*)(P + (ty * 4 + r) * XLD + k0 + g * 4);
                bv[r] = *(const float4*)(Q + (ty * 4 + r) * XLD + k0 + g * 4);
            }
#pragma unroll
            for (int kk = 0; kk < 4; kk++) {
                float xs[4];
                {
                    float wa[16];
#pragma unroll
                    for (int c = 0; c < 16; c++) wa[c] = Wb[(g * 4 + kk) * 512 + c * 16 + tx];
#pragma unroll
                    for (int r = 0; r < 4; r++) xs[r] = F4GET(av[r], kk);
#pragma unroll
                    for (int r = 0; r < 4; r++)
#pragma unroll
                        for (int c = 0; c < 16; c++) acc[r][c] = fmaf(xs[r], wa[c], acc[r][c]);
                }
                {
                    float wb[16];
#pragma unroll
                    for (int c = 0; c < 16; c++) wb[c] = Wb[(g * 4 + kk) * 512 + 256 + c * 16 + tx];
#pragma unroll
                    for (int r = 0; r < 4; r++) xs[r] = F4GET(bv[r], kk);
#pragma unroll
                    for (int r = 0; r < 4; r++)
#pragma unroll
                        for (int c = 0; c < 16; c++) acc[r][c] = fmaf(xs[r], wb[c], acc[r][c]);
                }
            }
        }
        __syncthreads();
        if (more) {
            float* d = sW + (buf ^ 1) * 4096 + tid * 16;
            *(float4*)d = n0; *(float4*)(d + 4) = n1;
            *(float4*)(d + 8) = n2; *(float4*)(d + 12) = n3;
        }
        buf ^= 1;
        __syncthreads();
    }

    float pr[4];
#pragma unroll
    for (int r = 0; r < 4; r++) {
        pr[r] = 0.f;
#pragma unroll
        for (int c = 0; c < 16; c++) {
            float h = fmaxf(acc[r][c], 0.f);
            pr[r] = fmaf(h, sFc2[c * 16 + tx], pr[r]);
        }
    }
#pragma unroll
    for (int off = 8; off >= 1; off >>= 1)
#pragma unroll
        for (int r = 0; r < 4; r++) pr[r] += __shfl_down_sync(0xffffffffu, pr[r], off, 16);
    if (tx == 0) {
#pragma unroll
        for (int r = 0; r < 4; r++)
            out[b * 256 + r0 + ty * 4 + r] = pr[r] + fc2b0;
    }
}

#define SMEM_FLOATS (2 * TM * XLD + 8192 + 4 * 256 + 2 * 64)
#define SMEM_BYTES  (SMEM_FLOATS * 4)

__global__ __launch_bounds__(256, 1)
void fused_chain(const float* __restrict__ fc1_b, const float* __restrict__ fc2_w,
                 const float* __restrict__ fc2_b, float* __restrict__ out) {
    extern __shared__ float sm[];
    float* P     = sm;                 // [TM][XLD]
    float* Q     = P + TM * XLD;       // [TM][XLD]
    float* sW    = Q + TM * XLD;       // 2 x 4096
    float* sAffA = sW + 8192;
    float* sAffV = sAffA + 256;
    float* sFc2  = sAffV + 256;
    float* sFb   = sFc2 + 256;
    float* sE1   = sFb + 256;
    float* sE2   = sE1 + 64;

    const int tid = threadIdx.x;
    const int b   = blockIdx.y;
    const int r0  = blockIdx.x * TM;
    const float scale = 0.0625f;   // 1/sqrt(256)

    sAffA[tid] = g_aff_a[b * 256 + tid];
    sAffV[tid] = g_aff_v[b * 256 + tid];
    sFc2[tid]  = fc2_w[tid];
    sFb[tid]   = fc1_b[tid];
    if (tid < TM) {
        sE1[tid] = g_enc1[b * 256 + r0 + tid];
        sE2[tid] = g_enc2[b * 256 + r0 + tid];
    }
    const float fc2b0 = fc2_b[0];
    __syncthreads();

    // attn_a tile -> P
    for (int idx = tid; idx < TM * 256; idx += 256) {
        int i = idx >> 8, m = idx & 255;
        P[i * XLD + m] = tanhf(sE1[i] * sAffA[m] * scale);
    }
    __syncthreads();

    // H_a = relu(attn_a @ wca^T + A1[i,:])  -> Q
    tile_gemm(P, g_wca_t, sW, Q, g_A1 + r0 * 256, true, tid);
    // ae1 = H_a @ wha^T + enc1[i,:]         -> P
    tile_gemm(Q, g_wha_t, sW, P, g_enc1 + r0 * 256, false, tid);

    // attn_v tile -> Q
    for (int idx = tid; idx < TM * 256; idx += 256) {
        int i = idx >> 8, m = idx & 255;
        Q[i * XLD + m] = tanhf(sE2[i] * sAffV[m] * scale);
    }
    __syncthreads();

    // H_v = relu(attn_v @ wcv^T + A2[i,:])  -> Q (in place)
    tile_gemm(Q, g_wcv_t, sW, Q, g_A2 + r0 * 256, true, tid);
    // ae2 = H_v @ whv^T + enc2[i,:]         -> Q (in place)
    tile_gemm(Q, g_whv_t, sW, Q, g_enc2 + r0 * 256, false, tid);

    // fc1 (both halves) + relu + fc2 reduction -> out
    fc_final(P, Q, sW, sFb, sFc2, fc2b0, out, b, r0, tid);
}

// ---------------- launch --------------------------------------------------
extern "C" void kernel_launch(void* const* d_in, const int* in_sizes, int n_in,
                              void* d_out, int out_size) {
    const float* features1 = (const float*)d_in[0];
    const float* features2 = (const float*)d_in[1];
    const float* enc1_w = (const float*)d_in[2];
    const float* enc1_b = (const float*)d_in[3];
    const float* enc2_w = (const float*)d_in[4];
    const float* enc2_b = (const float*)d_in[5];
    const float* affa_w = (const float*)d_in[6];
    const float* affv_w = (const float*)d_in[7];
    const float* wa_w   = (const float*)d_in[8];
    const float* wv_w   = (const float*)d_in[9];
    const float* wca_w  = (const float*)d_in[10];
    const float* wcv_w  = (const float*)d_in[11];
    const float* wha_w  = (const float*)d_in[12];
    const float* whv_w  = (const float*)d_in[13];
    const float* fc1_w  = (const float*)d_in[14];
    const float* fc1_b  = (const float*)d_in[15];
    const float* fc2_w  = (const float*)d_in[16];
    const float* fc2_b  = (const float*)d_in[17];
    float* out = (float*)d_out;

    float *p_enc1, *p_enc2, *p_aff_a, *p_aff_v, *p_A1, *p_A2;
    cudaGetSymbolAddress((void**)&p_enc1, g_enc1);
    cudaGetSymbolAddress((void**)&p_enc2, g_enc2);
    cudaGetSymbolAddress((void**)&p_aff_a, g_aff_a);
    cudaGetSymbolAddress((void**)&p_aff_v, g_aff_v);
    cudaGetSymbolAddress((void**)&p_A1, g_A1);
    cudaGetSymbolAddress((void**)&p_A2, g_A2);

    cudaFuncSetAttribute(fused_chain, cudaFuncAttributeMaxDynamicSharedMemorySize,
                         SMEM_BYTES);

    transpose_prep<<<dim3(8, 8, 6), dim3(32, 32)>>>(wca_w, wcv_w, wha_w, whv_w, fc1_w);

    gemm_nt<<<dim3(16, 16), dim3(16, 16)>>>(features1, enc1_w, enc1_b, p_enc1, 256, 256, 768);
    gemm_nt<<<dim3(16, 16), dim3(16, 16)>>>(features2, enc2_w, enc2_b, p_enc2, 256, 256, 768);

    gemm_nt<<<dim3(16, 16), dim3(16, 16)>>>(p_enc1, affa_w, nullptr, p_aff_a, 256, 256, 256);
    gemm_nt<<<dim3(16, 16), dim3(16, 16)>>>(p_enc2, affv_w, nullptr, p_aff_v, 256, 256, 256);
    gemm_nt<<<dim3(16, 16), dim3(16, 16)>>>(p_enc1, wa_w,   nullptr, p_A1,    256, 256, 256);
    gemm_nt<<<dim3(16, 16), dim3(16, 16)>>>(p_enc2, wv_w,   nullptr, p_A2,    256, 256, 256);

    fused_chain<<<dim3(256 / TM, 256), 256, SMEM_BYTES>>>(fc1_b, fc2_w, fc2_b, out);
}

// round 9
// speedup vs baseline: 1.4759x; 1.4759x over previous
#include <cuda_runtime.h>
#include <math.h>

#define EDIM 256
#define TM 64
#define XLD 260            // padded smem row stride for P/Q (multiple of 4)

typedef unsigned long long ull;

// ---- packed f32x2 helpers (Blackwell sm_100+) ------------------------------
__device__ __forceinline__ ull pack2(float x) {
    ull r; unsigned xi = __float_as_uint(x);
    asm("mov.b64 %0, {%1, %1};" : "=l"(r) : "r"(xi));
    return r;
}
__device__ __forceinline__ void ffma2(ull& d, ull a, ull b) {
    asm("fma.rn.f32x2 %0, %1, %2, %0;" : "+l"(d) : "l"(a), "l"(b));
}
__device__ __forceinline__ float lo32(ull v) { return __uint_as_float((unsigned)v); }
__device__ __forceinline__ float hi32(ull v) { return __uint_as_float((unsigned)(v >> 32)); }

#define F4GET(v, kk) ((kk) == 0 ? (v).x : (kk) == 1 ? (v).y : (kk) == 2 ? (v).z : (v).w)

// ---------------- device-global scratch (allocation-free workaround) --------
__device__ float g_enc1[EDIM*EDIM], g_enc2[EDIM*EDIM];
__device__ float g_aff_a[EDIM*EDIM], g_aff_v[EDIM*EDIM];
__device__ float g_A1[EDIM*EDIM],  g_A2[EDIM*EDIM];
__device__ float g_wca_t[EDIM*EDIM], g_wcv_t[EDIM*EDIM];
__device__ float g_wha_t[EDIM*EDIM], g_whv_t[EDIM*EDIM];
__device__ float g_fc1a_t[EDIM*EDIM], g_fc1b_t[EDIM*EDIM];

// ---------------- prep: transpose weights to k-major ------------------------
__global__ void transpose_prep(const float* __restrict__ wca,
                               const float* __restrict__ wcv,
                               const float* __restrict__ wha,
                               const float* __restrict__ whv,
                               const float* __restrict__ fc1) {
    __shared__ float t[32][33];
    int z = blockIdx.z;
    const float* src; int ld; float* dst;
    switch (z) {
        case 0: src = wca;       ld = 256; dst = g_wca_t;  break;
        case 1: src = wcv;       ld = 256; dst = g_wcv_t;  break;
        case 2: src = wha;       ld = 256; dst = g_wha_t;  break;
        case 3: src = whv;       ld = 256; dst = g_whv_t;  break;
        case 4: src = fc1;       ld = 512; dst = g_fc1a_t; break;
        default: src = fc1 + 256; ld = 512; dst = g_fc1b_t; break;
    }
    int j = blockIdx.y * 32 + threadIdx.y;   // source row
    int k = blockIdx.x * 32 + threadIdx.x;   // source col
    t[threadIdx.y][threadIdx.x] = src[j * ld + k];
    __syncthreads();
    int ko = blockIdx.x * 32 + threadIdx.y;
    int jo = blockIdx.y * 32 + threadIdx.x;
    dst[ko * 256 + jo] = t[threadIdx.x][threadIdx.y];
}

// ---------------- prologue GEMM body: C = A @ B^T (+bias), scalar -----------
__device__ __forceinline__ void gemm_body_s(const float* __restrict__ A,
                                            const float* __restrict__ B,
                                            const float* __restrict__ bias,
                                            float* __restrict__ C, int K) {
    __shared__ float As[16][17], Bs[16][17];
    int tx = threadIdx.x, ty = threadIdx.y;
    int row = blockIdx.y * 16 + ty;
    int col = blockIdx.x * 16 + tx;
    float acc = 0.f;
    for (int k0 = 0; k0 < K; k0 += 16) {
        As[ty][tx] = A[row * K + k0 + tx];
        Bs[ty][tx] = B[(blockIdx.x * 16 + ty) * K + k0 + tx];
        __syncthreads();
#pragma unroll
        for (int kk = 0; kk < 16; kk++) acc = fmaf(As[ty][kk], Bs[tx][kk], acc);
        __syncthreads();
    }
    C[row * 256 + col] = acc + (bias ? bias[col] : 0.f);
}

__global__ void enc_gemms(const float* __restrict__ f1, const float* __restrict__ f2,
                          const float* __restrict__ w1, const float* __restrict__ b1,
                          const float* __restrict__ w2, const float* __restrict__ b2) {
    if (blockIdx.z == 0) gemm_body_s(f1, w1, b1, g_enc1, 768);
    else                 gemm_body_s(f2, w2, b2, g_enc2, 768);
}

__global__ void quad_gemms(const float* __restrict__ affa, const float* __restrict__ affv,
                           const float* __restrict__ wa,   const float* __restrict__ wv) {
    switch (blockIdx.z) {
        case 0: gemm_body_s(g_enc1, affa, nullptr, g_aff_a, 256); break;
        case 1: gemm_body_s(g_enc2, affv, nullptr, g_aff_v, 256); break;
        case 2: gemm_body_s(g_enc1, wa,   nullptr, g_A1,    256); break;
        default: gemm_body_s(g_enc2, wv,  nullptr, g_A2,    256); break;
    }
}

// ---------------- fused chain: one 64x256 tile GEMM step (f32x2) ------------
// dst[i][j] = epi( sum_k X[i][k]*Wt[k][j] + gAdd[i*256+j] ); X,dst in smem.
// Thread map: tx=tid&15, ty=tid>>4; rows i = ty*4+r (r<4); cols j = cc*64+tx*4+{0..3}.
// Double buffer, ONE barrier per 16-row k-chunk: store(buf^1) is disjoint from
// compute(buf); WAR vs previous chunk's reads of buf^1 is fenced by that
// chunk's trailing barrier. In-place dst==X safe: stores after final barrier.
__device__ __forceinline__ void tile_gemm_p(const float* __restrict__ X,
                                            const float* __restrict__ Wt,
                                            float* __restrict__ sW,
                                            float* __restrict__ dst,
                                            const float* __restrict__ gAdd,
                                            bool do_relu, int tid) {
    const int tx = tid & 15, ty = tid >> 4;
    const int sc4 = tx * 4;

    ull acc[4][8];
#pragma unroll
    for (int r = 0; r < 4; r++)
#pragma unroll
        for (int c = 0; c < 8; c++) acc[r][c] = 0ull;

    // stage chunk 0: 16 rows x 256 cols
    {
        const float* s = Wt + ty * 256 + sc4;
        float* d = sW + ty * 256 + sc4;
#pragma unroll
        for (int u = 0; u < 4; u++)
            *(float4*)(d + u * 64) = *(const float4*)(s + u * 64);
    }
    __syncthreads();

    int buf = 0;
    for (int k0 = 0; k0 < 256; k0 += 16) {
        const bool more = (k0 + 16) < 256;
        float4 n0, n1, n2, n3;
        if (more) {
            const float* s = Wt + (k0 + 16 + ty) * 256 + sc4;
            n0 = *(const float4*)s;         n1 = *(const float4*)(s + 64);
            n2 = *(const float4*)(s + 128); n3 = *(const float4*)(s + 192);
        }
        const float* Wb = sW + buf * 4096;
#pragma unroll
        for (int g = 0; g < 4; g++) {
            float4 xv[4];
#pragma unroll
            for (int r = 0; r < 4; r++)
                xv[r] = *(const float4*)(X + (ty * 4 + r) * XLD + k0 + g * 4);
#pragma unroll
            for (int kk = 0; kk < 4; kk++) {
                const float* wrow = Wb + (g * 4 + kk) * 256 + sc4;
                ull w[8];
#pragma unroll
                for (int cc = 0; cc < 4; cc++) {
                    ulonglong2 wv = *(const ulonglong2*)(wrow + cc * 64);
                    w[cc * 2] = wv.x; w[cc * 2 + 1] = wv.y;
                }
#pragma unroll
                for (int r = 0; r < 4; r++) {
                    ull xp = pack2(F4GET(xv[r], kk));
#pragma unroll
                    for (int c = 0; c < 8; c++) ffma2(acc[r][c], xp, w[c]);
                }
            }
        }
        if (more) {
            float* d = sW + (buf ^ 1) * 4096 + ty * 256 + sc4;
            *(float4*)d = n0; *(float4*)(d + 64) = n1;
            *(float4*)(d + 128) = n2; *(float4*)(d + 192) = n3;
        }
        buf ^= 1;
        __syncthreads();
    }

    // epilogue
#pragma unroll
    for (int r = 0; r < 4; r++) {
        const int i = ty * 4 + r;
#pragma unroll
        for (int cc = 0; cc < 4; cc++) {
            const int j = cc * 64 + sc4;
            float4 gv = *(const float4*)(gAdd + i * 256 + j);
            float v0 = lo32(acc[r][cc * 2])     + gv.x;
            float v1 = hi32(acc[r][cc * 2])     + gv.y;
            float v2 = lo32(acc[r][cc * 2 + 1]) + gv.z;
            float v3 = hi32(acc[r][cc * 2 + 1]) + gv.w;
            if (do_relu) {
                v0 = fmaxf(v0, 0.f); v1 = fmaxf(v1, 0.f);
                v2 = fmaxf(v2, 0.f); v3 = fmaxf(v3, 0.f);
            }
            *(float4*)(dst + i * XLD + j) = make_float4(v0, v1, v2, v3);
        }
    }
    __syncthreads();
}

// h = relu(P@fc1a^T + Q@fc1b^T + b1); out = h . fc2 + b2
__device__ __forceinline__ void fc_final_p(const float* __restrict__ P,
                                           const float* __restrict__ Q,
                                           float* __restrict__ sW,
                                           const float* __restrict__ sFb,
                                           const float* __restrict__ sFc2,
                                           float fc2b0, float* __restrict__ out,
                                           int b, int r0, int tid) {
    const int tx = tid & 15, ty = tid >> 4;
    const int sc4 = tx * 4;

    ull acc[4][8];
#pragma unroll
    for (int r = 0; r < 4; r++)
#pragma unroll
        for (int c = 0; c < 8; c++) acc[r][c] = 0ull;

    // stage chunk 0: 16 rows x [fc1a | fc1b] (512 cols)
    {
        float* d = sW + ty * 512 + sc4;
#pragma unroll
        for (int u = 0; u < 4; u++) {
            *(float4*)(d + u * 64)       = *(const float4*)(g_fc1a_t + ty * 256 + sc4 + u * 64);
            *(float4*)(d + 256 + u * 64) = *(const float4*)(g_fc1b_t + ty * 256 + sc4 + u * 64);
        }
    }
    __syncthreads();

    int buf = 0;
    for (int k0 = 0; k0 < 256; k0 += 16) {
        const bool more = (k0 + 16) < 256;
        float4 na[4], nb[4];
        if (more) {
            const float* sa = g_fc1a_t + (k0 + 16 + ty) * 256 + sc4;
            const float* sb = g_fc1b_t + (k0 + 16 + ty) * 256 + sc4;
#pragma unroll
            for (int u = 0; u < 4; u++) {
                na[u] = *(const float4*)(sa + u * 64);
                nb[u] = *(const float4*)(sb + u * 64);
            }
        }
        const float* Wb = sW + buf * 8192;
#pragma unroll
        for (int g = 0; g < 4; g++) {
            float4 pv[4], qv[4];
#pragma unroll
            for (int r = 0; r < 4; r++) {
                pv[r] = *(const float4*)(P + (ty * 4 + r) * XLD + k0 + g * 4);
                qv[r] = *(const float4*)(Q + (ty * 4 + r) * XLD + k0 + g * 4);
            }
#pragma unroll
            for (int kk = 0; kk < 4; kk++) {
                const float* wrow = Wb + (g * 4 + kk) * 512 + sc4;
                {
                    ull w[8];
#pragma unroll
                    for (int cc = 0; cc < 4; cc++) {
                        ulonglong2 wv = *(const ulonglong2*)(wrow + cc * 64);
                        w[cc * 2] = wv.x; w[cc * 2 + 1] = wv.y;
                    }
#pragma unroll
                    for (int r = 0; r < 4; r++) {
                        ull xp = pack2(F4GET(pv[r], kk));
#pragma unroll
                        for (int c = 0; c < 8; c++) ffma2(acc[r][c], xp, w[c]);
                    }
                }
                {
                    ull w[8];
#pragma unroll
                    for (int cc = 0; cc < 4; cc++) {
                        ulonglong2 wv = *(const ulonglong2*)(wrow + 256 + cc * 64);
                        w[cc * 2] = wv.x; w[cc * 2 + 1] = wv.y;
                    }
#pragma unroll
                    for (int r = 0; r < 4; r++) {
                        ull xp = pack2(F4GET(qv[r], kk));
#pragma unroll
                        for (int c = 0; c < 8; c++) ffma2(acc[r][c], xp, w[c]);
                    }
                }
            }
        }
        if (more) {
            float* d = sW + (buf ^ 1) * 8192 + ty * 512 + sc4;
#pragma unroll
            for (int u = 0; u < 4; u++) {
                *(float4*)(d + u * 64)       = na[u];
                *(float4*)(d + 256 + u * 64) = nb[u];
            }
        }
        buf ^= 1;
        __syncthreads();
    }

    // epilogue: relu + bias, dot with fc2, reduce across the 16 tx lanes
    float pr[4] = {0.f, 0.f, 0.f, 0.f};
#pragma unroll
    for (int cc = 0; cc < 4; cc++) {
        const int j = cc * 64 + sc4;
        float4 fb = *(const float4*)(sFb + j);
        float4 f2 = *(const float4*)(sFc2 + j);
#pragma unroll
        for (int r = 0; r < 4; r++) {
            float h0 = fmaxf(lo32(acc[r][cc * 2])     + fb.x, 0.f);
            float h1 = fmaxf(hi32(acc[r][cc * 2])     + fb.y, 0.f);
            float h2 = fmaxf(lo32(acc[r][cc * 2 + 1]) + fb.z, 0.f);
            float h3 = fmaxf(hi32(acc[r][cc * 2 + 1]) + fb.w, 0.f);
            pr[r] = fmaf(h0, f2.x, fmaf(h1, f2.y, fmaf(h2, f2.z, fmaf(h3, f2.w, pr[r]))));
        }
    }
#pragma unroll
    for (int off = 8; off >= 1; off >>= 1)
#pragma unroll
        for (int r = 0; r < 4; r++)
            pr[r] += __shfl_down_sync(0xffffffffu, pr[r], off, 16);
    if (tx == 0) {
#pragma unroll
        for (int r = 0; r < 4; r++)
            out[b * 256 + r0 + ty * 4 + r] = pr[r] + fc2b0;
    }
}

#define SMEM_FLOATS (2 * TM * XLD + 2 * 8192 + 4 * 256 + 2 * 64)
#define SMEM_BYTES  (SMEM_FLOATS * 4)

__global__ __launch_bounds__(256, 1)
void fused_chain(const float* __restrict__ fc1_b, const float* __restrict__ fc2_w,
                 const float* __restrict__ fc2_b, float* __restrict__ out) {
    extern __shared__ float sm[];
    float* P     = sm;                 // [TM][XLD]
    float* Q     = P + TM * XLD;       // [TM][XLD]
    float* sW    = Q + TM * XLD;       // 2 x 8192 (chain uses 2 x 4096 of it)
    float* sAffA = sW + 2 * 8192;
    float* sAffV = sAffA + 256;
    float* sFc2  = sAffV + 256;
    float* sFb   = sFc2 + 256;
    float* sE1   = sFb + 256;
    float* sE2   = sE1 + 64;

    const int tid = threadIdx.x;
    const int b   = blockIdx.y;
    const int r0  = blockIdx.x * TM;
    const float scale = 0.0625f;   // 1/sqrt(256)

    sAffA[tid] = g_aff_a[b * 256 + tid];
    sAffV[tid] = g_aff_v[b * 256 + tid];
    sFc2[tid]  = fc2_w[tid];
    sFb[tid]   = fc1_b[tid];
    if (tid < TM) {
        sE1[tid] = g_enc1[b * 256 + r0 + tid];
        sE2[tid] = g_enc2[b * 256 + r0 + tid];
    }
    const float fc2b0 = fc2_b[0];
    __syncthreads();

    // attn_a tile -> P
    for (int idx = tid; idx < TM * 256; idx += 256) {
        int i = idx >> 8, m = idx & 255;
        P[i * XLD + m] = tanhf(sE1[i] * sAffA[m] * scale);
    }
    __syncthreads();

    // H_a = relu(attn_a @ wca^T + A1[i,:])  -> Q
    tile_gemm_p(P, g_wca_t, sW, Q, g_A1 + r0 * 256, true, tid);
    // ae1 = H_a @ wha^T + enc1[i,:]         -> P
    tile_gemm_p(Q, g_wha_t, sW, P, g_enc1 + r0 * 256, false, tid);

    // attn_v tile -> Q
    for (int idx = tid; idx < TM * 256; idx += 256) {
        int i = idx >> 8, m = idx & 255;
        Q[i * XLD + m] = tanhf(sE2[i] * sAffV[m] * scale);
    }
    __syncthreads();

    // H_v = relu(attn_v @ wcv^T + A2[i,:])  -> Q (in place)
    tile_gemm_p(Q, g_wcv_t, sW, Q, g_A2 + r0 * 256, true, tid);
    // ae2 = H_v @ whv^T + enc2[i,:]         -> Q (in place)
    tile_gemm_p(Q, g_whv_t, sW, Q, g_enc2 + r0 * 256, false, tid);

    // fc1 (both halves) + relu + fc2 reduction -> out
    fc_final_p(P, Q, sW, sFb, sFc2, fc2b0, out, b, r0, tid);
}

// ---------------- launch --------------------------------------------------
extern "C" void kernel_launch(void* const* d_in, const int* in_sizes, int n_in,
                              void* d_out, int out_size) {
    const float* features1 = (const float*)d_in[0];
    const float* features2 = (const float*)d_in[1];
    const float* enc1_w = (const float*)d_in[2];
    const float* enc1_b = (const float*)d_in[3];
    const float* enc2_w = (const float*)d_in[4];
    const float* enc2_b = (const float*)d_in[5];
    const float* affa_w = (const float*)d_in[6];
    const float* affv_w = (const float*)d_in[7];
    const float* wa_w   = (const float*)d_in[8];
    const float* wv_w   = (const float*)d_in[9];
    const float* wca_w  = (const float*)d_in[10];
    const float* wcv_w  = (const float*)d_in[11];
    const float* wha_w  = (const float*)d_in[12];
    const float* whv_w  = (const float*)d_in[13];
    const float* fc1_w  = (const float*)d_in[14];
    const float* fc1_b  = (const float*)d_in[15];
    const float* fc2_w  = (const float*)d_in[16];
    const float* fc2_b  = (const float*)d_in[17];
    float* out = (float*)d_out;

    cudaFuncSetAttribute(fused_chain, cudaFuncAttributeMaxDynamicSharedMemorySize,
                         SMEM_BYTES);

    transpose_prep<<<dim3(8, 8, 6), dim3(32, 32)>>>(wca_w, wcv_w, wha_w, whv_w, fc1_w);

    enc_gemms<<<dim3(16, 16, 2), dim3(16, 16)>>>(features1, features2,
                                                 enc1_w, enc1_b, enc2_w, enc2_b);
    quad_gemms<<<dim3(16, 16, 4), dim3(16, 16)>>>(affa_w, affv_w, wa_w, wv_w);

    fused_chain<<<dim3(256 / TM, 256), 256, SMEM_BYTES>>>(fc1_b, fc2_w, fc2_b, out);
}

// round 11
// speedup vs baseline: 1.5780x; 1.0692x over previous
#include <cuda_runtime.h>
#include <math.h>

#define EDIM 256
#define TM 64
#define XLD 260            // P/Q smem row stride (A-frag banks (4g+tig): conflict-free)
#define CW_LD 264          // chain weight stage row stride (8*tig+g: conflict-free)
#define FW_LD 520          // fc weight stage row stride (520%32==8: same pattern)
#define WBUF 8320          // floats per weight stage buffer (16*FW_LD); chain uses 16*CW_LD

// round fp32 -> tf32 (rna)
__device__ __forceinline__ float tf32r(float x) {
    unsigned int o;
    asm("cvt.rna.tf32.f32 %0, %1;\n" : "=r"(o) : "f"(x));
    return __uint_as_float(o);
}

// raw PTX tensor-core mma: D[16x8] += A[16x8] * B[8x8], tf32 inputs, f32 accum
__device__ __forceinline__ void mma_tf32(float* c,
                                         unsigned a0, unsigned a1, unsigned a2, unsigned a3,
                                         unsigned b0, unsigned b1) {
    asm("mma.sync.aligned.m16n8k8.row.col.f32.tf32.tf32.f32 "
        "{%0,%1,%2,%3}, {%4,%5,%6,%7}, {%8,%9}, {%0,%1,%2,%3};"
        : "+f"(c[0]), "+f"(c[1]), "+f"(c[2]), "+f"(c[3])
        : "r"(a0), "r"(a1), "r"(a2), "r"(a3), "r"(b0), "r"(b1));
}

__device__ __forceinline__ unsigned fbits(float x) { return __float_as_uint(x); }

// ---------------- device-global scratch (allocation-free workaround) --------
__device__ float g_enc1[EDIM*EDIM], g_enc2[EDIM*EDIM];
__device__ float g_aff_a[EDIM*EDIM], g_aff_v[EDIM*EDIM];
__device__ float g_A1[EDIM*EDIM],  g_A2[EDIM*EDIM];
__device__ float g_wca_t[EDIM*EDIM], g_wcv_t[EDIM*EDIM];
__device__ float g_wha_t[EDIM*EDIM], g_whv_t[EDIM*EDIM];
__device__ float g_fc1a_t[EDIM*EDIM], g_fc1b_t[EDIM*EDIM];

// ---------------- prep: transpose weights to k-major, round to tf32 ---------
__global__ void transpose_prep(const float* __restrict__ wca,
                               const float* __restrict__ wcv,
                               const float* __restrict__ wha,
                               const float* __restrict__ whv,
                               const float* __restrict__ fc1) {
    __shared__ float t[32][33];
    int z = blockIdx.z;
    const float* src; int ld; float* dst;
    switch (z) {
        case 0: src = wca;       ld = 256; dst = g_wca_t;  break;
        case 1: src = wcv;       ld = 256; dst = g_wcv_t;  break;
        case 2: src = wha;       ld = 256; dst = g_wha_t;  break;
        case 3: src = whv;       ld = 256; dst = g_whv_t;  break;
        case 4: src = fc1;       ld = 512; dst = g_fc1a_t; break;
        default: src = fc1 + 256; ld = 512; dst = g_fc1b_t; break;
    }
    int j = blockIdx.y * 32 + threadIdx.y;   // source row
    int k = blockIdx.x * 32 + threadIdx.x;   // source col
    t[threadIdx.y][threadIdx.x] = src[j * ld + k];
    __syncthreads();
    int ko = blockIdx.x * 32 + threadIdx.y;
    int jo = blockIdx.y * 32 + threadIdx.x;
    dst[ko * 256 + jo] = tf32r(t[threadIdx.x][threadIdx.y]);
}

// ---------------- prologue GEMM body: C = A @ B^T (+bias), scalar (KNOWN GOOD)
__device__ __forceinline__ void gemm_body_s(const float* __restrict__ A,
                                            const float* __restrict__ B,
                                            const float* __restrict__ bias,
                                            float* __restrict__ C, int K) {
    __shared__ float As[16][17], Bs[16][17];
    int tx = threadIdx.x, ty = threadIdx.y;
    int row = blockIdx.y * 16 + ty;
    int col = blockIdx.x * 16 + tx;
    float acc = 0.f;
    for (int k0 = 0; k0 < K; k0 += 16) {
        As[ty][tx] = A[row * K + k0 + tx];
        Bs[ty][tx] = B[(blockIdx.x * 16 + ty) * K + k0 + tx];
        __syncthreads();
#pragma unroll
        for (int kk = 0; kk < 16; kk++) acc = fmaf(As[ty][kk], Bs[tx][kk], acc);
        __syncthreads();
    }
    C[row * 256 + col] = acc + (bias ? bias[col] : 0.f);
}

__global__ void enc_gemms(const float* __restrict__ f1, const float* __restrict__ f2,
                          const float* __restrict__ w1, const float* __restrict__ b1,
                          const float* __restrict__ w2, const float* __restrict__ b2) {
    if (blockIdx.z == 0) gemm_body_s(f1, w1, b1, g_enc1, 768);
    else                 gemm_body_s(f2, w2, b2, g_enc2, 768);
}

__global__ void quad_gemms(const float* __restrict__ affa, const float* __restrict__ affv,
                           const float* __restrict__ wa,   const float* __restrict__ wv) {
    switch (blockIdx.z) {
        case 0: gemm_body_s(g_enc1, affa, nullptr, g_aff_a, 256); break;
        case 1: gemm_body_s(g_enc2, affv, nullptr, g_aff_v, 256); break;
        case 2: gemm_body_s(g_enc1, wa,   nullptr, g_A1,    256); break;
        default: gemm_body_s(g_enc2, wv,  nullptr, g_A2,    256); break;
    }
}

// ---------------- fused chain: one 64x256 tile GEMM step (PTX mma tf32) -----
// dst[i][j] = epi( sum_k X[i][k]*Wt[k][j] + gAdd[i*256+j] ); X,dst in smem.
// 8 warps: wr=wid&3 (16-row tile), wc=wid>>2 (128-col tile); m16n8k8 frags.
// Double buffer, ONE barrier per 16-row k-chunk (same discipline as R9).
// In-place dst==X safe: acc stores happen after the loop-end barrier.
__device__ __forceinline__ void tile_gemm_mma(const float* __restrict__ X,
                                              const float* __restrict__ Wt,
                                              float* __restrict__ sW,
                                              float* __restrict__ dst,
                                              const float* __restrict__ gAdd,
                                              bool do_relu, int tid) {
    const int lane = tid & 31, wid = tid >> 5;
    const int wr = wid & 3, wc = wid >> 2;
    const int g = lane >> 2, tig = lane & 3;
    const int srow = tid >> 4, scol = (tid & 15) * 16;

    float acc[16][4];
#pragma unroll
    for (int nt = 0; nt < 16; nt++)
#pragma unroll
        for (int e = 0; e < 4; e++) acc[nt][e] = 0.f;

    // stage chunk 0: 16 rows x 256 -> sW (stride CW_LD)
    {
        const float* s = Wt + srow * 256 + scol;
        float* d = sW + srow * CW_LD + scol;
#pragma unroll
        for (int u = 0; u < 4; u++)
            *(float4*)(d + u * 4) = *(const float4*)(s + u * 4);
    }
    __syncthreads();

    int buf = 0;
#pragma unroll 1
    for (int k0 = 0; k0 < 256; k0 += 16) {
        const bool more = (k0 + 16) < 256;
        float4 n0, n1, n2, n3;
        if (more) {
            const float* s = Wt + (k0 + 16 + srow) * 256 + scol;
            n0 = *(const float4*)s;       n1 = *(const float4*)(s + 4);
            n2 = *(const float4*)(s + 8); n3 = *(const float4*)(s + 12);
        }
        const float* Wb = sW + buf * WBUF;
#pragma unroll
        for (int ks = 0; ks < 16; ks += 8) {
            const float* Xr = X + (wr * 16 + g) * XLD + k0 + ks + tig;
            unsigned a0 = fbits(Xr[0]);
            unsigned a1 = fbits(Xr[8 * XLD]);
            unsigned a2 = fbits(Xr[4]);
            unsigned a3 = fbits(Xr[8 * XLD + 4]);
            const float* Bb = Wb + (ks + tig) * CW_LD + wc * 128 + g;
#pragma unroll
            for (int nt = 0; nt < 16; nt++) {
                unsigned b0 = fbits(Bb[nt * 8]);
                unsigned b1 = fbits(Bb[nt * 8 + 4 * CW_LD]);
                mma_tf32(acc[nt], a0, a1, a2, a3, b0, b1);
            }
        }
        if (more) {
            float* d = sW + (buf ^ 1) * WBUF + srow * CW_LD + scol;
            *(float4*)d = n0; *(float4*)(d + 4) = n1;
            *(float4*)(d + 8) = n2; *(float4*)(d + 12) = n3;
        }
        buf ^= 1;
        __syncthreads();
    }

    // spill accumulators to dst (raw), then elementwise epilogue
#pragma unroll
    for (int nt = 0; nt < 16; nt++) {
        const int c0 = wc * 128 + nt * 8 + 2 * tig;
        const int r = wr * 16 + g;
        *(float2*)(dst + r * XLD + c0)       = make_float2(acc[nt][0], acc[nt][1]);
        *(float2*)(dst + (r + 8) * XLD + c0) = make_float2(acc[nt][2], acc[nt][3]);
    }
    __syncthreads();
    for (int idx = tid; idx < TM * 256; idx += 256) {
        int i = idx >> 8, j = idx & 255;
        float v = dst[i * XLD + j] + gAdd[i * 256 + j];
        if (do_relu) v = fmaxf(v, 0.f);
        dst[i * XLD + j] = tf32r(v);
    }
    __syncthreads();
}

// h = relu(P@fc1a^T + Q@fc1b^T + b1); out = h . fc2 + b2. scr aliases P.
__device__ __forceinline__ void fc_final_mma(const float* __restrict__ P,
                                             const float* __restrict__ Q,
                                             float* __restrict__ sW,
                                             float* __restrict__ scr,
                                             const float* __restrict__ sFb,
                                             const float* __restrict__ sFc2,
                                             float fc2b0, float* __restrict__ out,
                                             int b, int r0, int tid) {
    const int lane = tid & 31, wid = tid >> 5;
    const int wr = wid & 3, wc = wid >> 2;
    const int g = lane >> 2, tig = lane & 3;
    const int srow = tid >> 4, scol = (tid & 15) * 32;

    float acc[16][4];
#pragma unroll
    for (int nt = 0; nt < 16; nt++)
#pragma unroll
        for (int e = 0; e < 4; e++) acc[nt][e] = 0.f;

    // stage chunk 0: 16 rows x [fc1a | fc1b] (512 cols) -> sW (stride FW_LD)
    {
        const float* s = (scol < 256) ? (g_fc1a_t + srow * 256 + scol)
                                      : (g_fc1b_t + srow * 256 + (scol - 256));
        float* d = sW + srow * FW_LD + scol;
#pragma unroll
        for (int u = 0; u < 8; u++)
            *(float4*)(d + u * 4) = *(const float4*)(s + u * 4);
    }
    __syncthreads();

    int buf = 0;
#pragma unroll 1
    for (int k0 = 0; k0 < 256; k0 += 16) {
        const bool more = (k0 + 16) < 256;
        float4 nv[8];
        if (more) {
            const float* s = (scol < 256) ? (g_fc1a_t + (k0 + 16 + srow) * 256 + scol)
                                          : (g_fc1b_t + (k0 + 16 + srow) * 256 + (scol - 256));
#pragma unroll
            for (int u = 0; u < 8; u++) nv[u] = *(const float4*)(s + u * 4);
        }
        const float* Wb = sW + buf * WBUF;
#pragma unroll
        for (int ks = 0; ks < 8; ks += 8) {  // two k8 subtiles handled below
#pragma unroll
            for (int half = 0; half < 2; half++) {
                const int kk = k0 + half * 8;
                const float* Pr = P + (wr * 16 + g) * XLD + kk + tig;
                const float* Qr = Q + (wr * 16 + g) * XLD + kk + tig;
                unsigned pa0 = fbits(Pr[0]), pa1 = fbits(Pr[8 * XLD]);
                unsigned pa2 = fbits(Pr[4]), pa3 = fbits(Pr[8 * XLD + 4]);
                unsigned qa0 = fbits(Qr[0]), qa1 = fbits(Qr[8 * XLD]);
                unsigned qa2 = fbits(Qr[4]), qa3 = fbits(Qr[8 * XLD + 4]);
                const float* Bp = Wb + (half * 8 + tig) * FW_LD + wc * 128 + g;
                const float* Bq = Bp + 256;
#pragma unroll
                for (int nt = 0; nt < 16; nt++) {
                    unsigned b0 = fbits(Bp[nt * 8]);
                    unsigned b1 = fbits(Bp[nt * 8 + 4 * FW_LD]);
                    mma_tf32(acc[nt], pa0, pa1, pa2, pa3, b0, b1);
                    unsigned c0 = fbits(Bq[nt * 8]);
                    unsigned c1 = fbits(Bq[nt * 8 + 4 * FW_LD]);
                    mma_tf32(acc[nt], qa0, qa1, qa2, qa3, c0, c1);
                }
            }
        }
        if (more) {
            float* d = sW + (buf ^ 1) * WBUF + srow * FW_LD + scol;
#pragma unroll
            for (int u = 0; u < 8; u++) *(float4*)(d + u * 4) = nv[u];
        }
        buf ^= 1;
        __syncthreads();
    }

    // spill acc to scr, then relu+bias+fc2 reduction
#pragma unroll
    for (int nt = 0; nt < 16; nt++) {
        const int c0 = wc * 128 + nt * 8 + 2 * tig;
        const int r = wr * 16 + g;
        *(float2*)(scr + r * XLD + c0)       = make_float2(acc[nt][0], acc[nt][1]);
        *(float2*)(scr + (r + 8) * XLD + c0) = make_float2(acc[nt][2], acc[nt][3]);
    }
    __syncthreads();

    const int row = tid >> 2, q = tid & 3;
    float s = 0.f;
    const float* rp = scr + row * XLD;
#pragma unroll 8
    for (int j = q * 64; j < q * 64 + 64; j++) {
        float h = fmaxf(rp[j] + sFb[j], 0.f);
        s = fmaf(h, sFc2[j], s);
    }
    s += __shfl_xor_sync(0xffffffffu, s, 1);
    s += __shfl_xor_sync(0xffffffffu, s, 2);
    if (q == 0) out[b * 256 + r0 + row] = s + fc2b0;
}

#define SMEM_FLOATS (2 * TM * XLD + 2 * WBUF + 4 * 256 + 2 * 64)
#define SMEM_BYTES  (SMEM_FLOATS * 4)

__global__ __launch_bounds__(256, 1)
void fused_chain(const float* __restrict__ fc1_b, const float* __restrict__ fc2_w,
                 const float* __restrict__ fc2_b, float* __restrict__ out) {
    extern __shared__ float sm[];
    float* P     = sm;                 // [TM][XLD]
    float* Q     = P + TM * XLD;       // [TM][XLD]
    float* sW    = Q + TM * XLD;       // 2 x WBUF
    float* sAffA = sW + 2 * WBUF;
    float* sAffV = sAffA + 256;
    float* sFc2  = sAffV + 256;
    float* sFb   = sFc2 + 256;
    float* sE1   = sFb + 256;
    float* sE2   = sE1 + 64;

    const int tid = threadIdx.x;
    const int b   = blockIdx.y;
    const int r0  = blockIdx.x * TM;
    const float scale = 0.0625f;   // 1/sqrt(256)

    sAffA[tid] = g_aff_a[b * 256 + tid];
    sAffV[tid] = g_aff_v[b * 256 + tid];
    sFc2[tid]  = fc2_w[tid];
    sFb[tid]   = fc1_b[tid];
    if (tid < TM) {
        sE1[tid] = g_enc1[b * 256 + r0 + tid];
        sE2[tid] = g_enc2[b * 256 + r0 + tid];
    }
    const float fc2b0 = fc2_b[0];
    __syncthreads();

    // attn_a tile -> P  (tf32-rounded)
    for (int idx = tid; idx < TM * 256; idx += 256) {
        int i = idx >> 8, m = idx & 255;
        P[i * XLD + m] = tf32r(tanhf(sE1[i] * sAffA[m] * scale));
    }
    __syncthreads();

    // H_a = relu(attn_a @ wca^T + A1[i,:])  -> Q
    tile_gemm_mma(P, g_wca_t, sW, Q, g_A1 + r0 * 256, true, tid);
    // ae1 = H_a @ wha^T + enc1[i,:]         -> P
    tile_gemm_mma(Q, g_wha_t, sW, P, g_enc1 + r0 * 256, false, tid);

    // attn_v tile -> Q
    for (int idx = tid; idx < TM * 256; idx += 256) {
        int i = idx >> 8, m = idx & 255;
        Q[i * XLD + m] = tf32r(tanhf(sE2[i] * sAffV[m] * scale));
    }
    __syncthreads();

    // H_v = relu(attn_v @ wcv^T + A2[i,:])  -> Q (in place)
    tile_gemm_mma(Q, g_wcv_t, sW, Q, g_A2 + r0 * 256, true, tid);
    // ae2 = H_v @ whv^T + enc2[i,:]         -> Q (in place)
    tile_gemm_mma(Q, g_whv_t, sW, Q, g_enc2 + r0 * 256, false, tid);

    // fc1 (both halves) + relu + fc2 reduction -> out
    fc_final_mma(P, Q, sW, P /*scratch*/, sFb, sFc2, fc2b0, out, b, r0, tid);
}

// ---------------- launch --------------------------------------------------
extern "C" void kernel_launch(void* const* d_in, const int* in_sizes, int n_in,
                              void* d_out, int out_size) {
    const float* features1 = (const float*)d_in[0];
    const float* features2 = (const float*)d_in[1];
    const float* enc1_w = (const float*)d_in[2];
    const float* enc1_b = (const float*)d_in[3];
    const float* enc2_w = (const float*)d_in[4];
    const float* enc2_b = (const float*)d_in[5];
    const float* affa_w = (const float*)d_in[6];
    const float* affv_w = (const float*)d_in[7];
    const float* wa_w   = (const float*)d_in[8];
    const float* wv_w   = (const float*)d_in[9];
    const float* wca_w  = (const float*)d_in[10];
    const float* wcv_w  = (const float*)d_in[11];
    const float* wha_w  = (const float*)d_in[12];
    const float* whv_w  = (const float*)d_in[13];
    const float* fc1_w  = (const float*)d_in[14];
    const float* fc1_b  = (const float*)d_in[15];
    const float* fc2_w  = (const float*)d_in[16];
    const float* fc2_b  = (const float*)d_in[17];
    float* out = (float*)d_out;

    cudaFuncSetAttribute(fused_chain, cudaFuncAttributeMaxDynamicSharedMemorySize,
                         SMEM_BYTES);

    transpose_prep<<<dim3(8, 8, 6), dim3(32, 32)>>>(wca_w, wcv_w, wha_w, whv_w, fc1_w);

    enc_gemms<<<dim3(16, 16, 2), dim3(16, 16)>>>(features1, features2,
                                                 enc1_w, enc1_b, enc2_w, enc2_b);
    quad_gemms<<<dim3(16, 16, 4), dim3(16, 16)>>>(affa_w, affv_w, wa_w, wv_w);

    fused_chain<<<dim3(256 / TM, 256), 256, SMEM_BYTES>>>(fc1_b, fc2_w, fc2_b, out);
}

// round 12
// speedup vs baseline: 1.5795x; 1.0010x over previous
#include <cuda_runtime.h>
#include <math.h>

#define EDIM 256
#define TM 64
#define XLD 260            // P/Q smem row stride (A-frag banks (4g+tig): conflict-free)
#define CW_LD 264          // chain weight stage row stride (8*tig+g: conflict-free)
#define FW_LD 520          // fc weight stage row stride (520%32==8: same pattern)
#define WBUF 8320          // floats per weight stage buffer (16*FW_LD); chain uses 16*CW_LD

// round fp32 -> tf32 (rna)
__device__ __forceinline__ float tf32r(float x) {
    unsigned int o;
    asm("cvt.rna.tf32.f32 %0, %1;\n" : "=r"(o) : "f"(x));
    return __uint_as_float(o);
}

// raw PTX tensor-core mma: D[16x8] += A[16x8] * B[8x8], tf32 inputs, f32 accum
__device__ __forceinline__ void mma_tf32(float* c,
                                         unsigned a0, unsigned a1, unsigned a2, unsigned a3,
                                         unsigned b0, unsigned b1) {
    asm("mma.sync.aligned.m16n8k8.row.col.f32.tf32.tf32.f32 "
        "{%0,%1,%2,%3}, {%4,%5,%6,%7}, {%8,%9}, {%0,%1,%2,%3};"
        : "+f"(c[0]), "+f"(c[1]), "+f"(c[2]), "+f"(c[3])
        : "r"(a0), "r"(a1), "r"(a2), "r"(a3), "r"(b0), "r"(b1));
}

__device__ __forceinline__ unsigned fbits(float x) { return __float_as_uint(x); }

// ---------------- device-global scratch (allocation-free workaround) --------
__device__ float g_enc1[EDIM*EDIM], g_enc2[EDIM*EDIM];
__device__ float g_aff_a[EDIM*EDIM], g_aff_v[EDIM*EDIM];
__device__ float g_A1[EDIM*EDIM],  g_A2[EDIM*EDIM];
__device__ float g_wca_t[EDIM*EDIM], g_wcv_t[EDIM*EDIM];
__device__ float g_wha_t[EDIM*EDIM], g_whv_t[EDIM*EDIM];
__device__ float g_fc1a_t[EDIM*EDIM], g_fc1b_t[EDIM*EDIM];

// ---------------- prep: transpose weights to k-major, round to tf32 ---------
__global__ void transpose_prep(const float* __restrict__ wca,
                               const float* __restrict__ wcv,
                               const float* __restrict__ wha,
                               const float* __restrict__ whv,
                               const float* __restrict__ fc1) {
    __shared__ float t[32][33];
    int z = blockIdx.z;
    const float* src; int ld; float* dst;
    switch (z) {
        case 0: src = wca;       ld = 256; dst = g_wca_t;  break;
        case 1: src = wcv;       ld = 256; dst = g_wcv_t;  break;
        case 2: src = wha;       ld = 256; dst = g_wha_t;  break;
        case 3: src = whv;       ld = 256; dst = g_whv_t;  break;
        case 4: src = fc1;       ld = 512; dst = g_fc1a_t; break;
        default: src = fc1 + 256; ld = 512; dst = g_fc1b_t; break;
    }
    int j = blockIdx.y * 32 + threadIdx.y;   // source row
    int k = blockIdx.x * 32 + threadIdx.x;   // source col
    t[threadIdx.y][threadIdx.x] = src[j * ld + k];
    __syncthreads();
    int ko = blockIdx.x * 32 + threadIdx.y;
    int jo = blockIdx.y * 32 + threadIdx.x;
    dst[ko * 256 + jo] = tf32r(t[threadIdx.x][threadIdx.y]);
}

// ---------------- prologue GEMM body: C = A @ B^T (+bias), scalar (KNOWN GOOD)
__device__ __forceinline__ void gemm_body_s(const float* __restrict__ A,
                                            const float* __restrict__ B,
                                            const float* __restrict__ bias,
                                            float* __restrict__ C, int K) {
    __shared__ float As[16][17], Bs[16][17];
    int tx = threadIdx.x, ty = threadIdx.y;
    int row = blockIdx.y * 16 + ty;
    int col = blockIdx.x * 16 + tx;
    float acc = 0.f;
    for (int k0 = 0; k0 < K; k0 += 16) {
        As[ty][tx] = A[row * K + k0 + tx];
        Bs[ty][tx] = B[(blockIdx.x * 16 + ty) * K + k0 + tx];
        __syncthreads();
#pragma unroll
        for (int kk = 0; kk < 16; kk++) acc = fmaf(As[ty][kk], Bs[tx][kk], acc);
        __syncthreads();
    }
    C[row * 256 + col] = acc + (bias ? bias[col] : 0.f);
}

__global__ void enc_gemms(const float* __restrict__ f1, const float* __restrict__ f2,
                          const float* __restrict__ w1, const float* __restrict__ b1,
                          const float* __restrict__ w2, const float* __restrict__ b2) {
    if (blockIdx.z == 0) gemm_body_s(f1, w1, b1, g_enc1, 768);
    else                 gemm_body_s(f2, w2, b2, g_enc2, 768);
}

__global__ void quad_gemms(const float* __restrict__ affa, const float* __restrict__ affv,
                           const float* __restrict__ wa,   const float* __restrict__ wv) {
    switch (blockIdx.z) {
        case 0: gemm_body_s(g_enc1, affa, nullptr, g_aff_a, 256); break;
        case 1: gemm_body_s(g_enc2, affv, nullptr, g_aff_v, 256); break;
        case 2: gemm_body_s(g_enc1, wa,   nullptr, g_A1,    256); break;
        default: gemm_body_s(g_enc2, wv,  nullptr, g_A2,    256); break;
    }
}

// ---------------- fused chain: one 64x256 tile GEMM step (PTX mma tf32) -----
// dst[i][j] = epi( sum_k X[i][k]*Wt[k][j] + gAdd[i*256+j] ); X,dst in smem.
// 8 warps: wr=wid&3 (16-row tile), wc=wid>>2 (128-col tile); m16n8k8 frags.
// Double buffer, ONE barrier per 16-row k-chunk (same discipline as R9).
// In-place dst==X safe: acc stores happen after the loop-end barrier.
__device__ __forceinline__ void tile_gemm_mma(const float* __restrict__ X,
                                              const float* __restrict__ Wt,
                                              float* __restrict__ sW,
                                              float* __restrict__ dst,
                                              const float* __restrict__ gAdd,
                                              bool do_relu, int tid) {
    const int lane = tid & 31, wid = tid >> 5;
    const int wr = wid & 3, wc = wid >> 2;
    const int g = lane >> 2, tig = lane & 3;
    const int srow = tid >> 4, scol = (tid & 15) * 16;

    float acc[16][4];
#pragma unroll
    for (int nt = 0; nt < 16; nt++)
#pragma unroll
        for (int e = 0; e < 4; e++) acc[nt][e] = 0.f;

    // stage chunk 0: 16 rows x 256 -> sW (stride CW_LD)
    {
        const float* s = Wt + srow * 256 + scol;
        float* d = sW + srow * CW_LD + scol;
#pragma unroll
        for (int u = 0; u < 4; u++)
            *(float4*)(d + u * 4) = *(const float4*)(s + u * 4);
    }
    __syncthreads();

    int buf = 0;
#pragma unroll 1
    for (int k0 = 0; k0 < 256; k0 += 16) {
        const bool more = (k0 + 16) < 256;
        float4 n0, n1, n2, n3;
        if (more) {
            const float* s = Wt + (k0 + 16 + srow) * 256 + scol;
            n0 = *(const float4*)s;       n1 = *(const float4*)(s + 4);
            n2 = *(const float4*)(s + 8); n3 = *(const float4*)(s + 12);
        }
        const float* Wb = sW + buf * WBUF;
#pragma unroll
        for (int ks = 0; ks < 16; ks += 8) {
            const float* Xr = X + (wr * 16 + g) * XLD + k0 + ks + tig;
            unsigned a0 = fbits(Xr[0]);
            unsigned a1 = fbits(Xr[8 * XLD]);
            unsigned a2 = fbits(Xr[4]);
            unsigned a3 = fbits(Xr[8 * XLD + 4]);
            const float* Bb = Wb + (ks + tig) * CW_LD + wc * 128 + g;
#pragma unroll
            for (int nt = 0; nt < 16; nt++) {
                unsigned b0 = fbits(Bb[nt * 8]);
                unsigned b1 = fbits(Bb[nt * 8 + 4 * CW_LD]);
                mma_tf32(acc[nt], a0, a1, a2, a3, b0, b1);
            }
        }
        if (more) {
            float* d = sW + (buf ^ 1) * WBUF + srow * CW_LD + scol;
            *(float4*)d = n0; *(float4*)(d + 4) = n1;
            *(float4*)(d + 8) = n2; *(float4*)(d + 12) = n3;
        }
        buf ^= 1;
        __syncthreads();
    }

    // spill accumulators to dst (raw), then elementwise epilogue
#pragma unroll
    for (int nt = 0; nt < 16; nt++) {
        const int c0 = wc * 128 + nt * 8 + 2 * tig;
        const int r = wr * 16 + g;
        *(float2*)(dst + r * XLD + c0)       = make_float2(acc[nt][0], acc[nt][1]);
        *(float2*)(dst + (r + 8) * XLD + c0) = make_float2(acc[nt][2], acc[nt][3]);
    }
    __syncthreads();
    for (int idx = tid; idx < TM * 256; idx += 256) {
        int i = idx >> 8, j = idx & 255;
        float v = dst[i * XLD + j] + gAdd[i * 256 + j];
        if (do_relu) v = fmaxf(v, 0.f);
        dst[i * XLD + j] = tf32r(v);
    }
    __syncthreads();
}

// h = relu(P@fc1a^T + Q@fc1b^T + b1); out = h . fc2 + b2. scr aliases P.
__device__ __forceinline__ void fc_final_mma(const float* __restrict__ P,
                                             const float* __restrict__ Q,
                                             float* __restrict__ sW,
                                             float* __restrict__ scr,
                                             const float* __restrict__ sFb,
                                             const float* __restrict__ sFc2,
                                             float fc2b0, float* __restrict__ out,
                                             int b, int r0, int tid) {
    const int lane = tid & 31, wid = tid >> 5;
    const int wr = wid & 3, wc = wid >> 2;
    const int g = lane >> 2, tig = lane & 3;
    const int srow = tid >> 4, scol = (tid & 15) * 32;

    float acc[16][4];
#pragma unroll
    for (int nt = 0; nt < 16; nt++)
#pragma unroll
        for (int e = 0; e < 4; e++) acc[nt][e] = 0.f;

    // stage chunk 0: 16 rows x [fc1a | fc1b] (512 cols) -> sW (stride FW_LD)
    {
        const float* s = (scol < 256) ? (g_fc1a_t + srow * 256 + scol)
                                      : (g_fc1b_t + srow * 256 + (scol - 256));
        float* d = sW + srow * FW_LD + scol;
#pragma unroll
        for (int u = 0; u < 8; u++)
            *(float4*)(d + u * 4) = *(const float4*)(s + u * 4);
    }
    __syncthreads();

    int buf = 0;
#pragma unroll 1
    for (int k0 = 0; k0 < 256; k0 += 16) {
        const bool more = (k0 + 16) < 256;
        float4 nv[8];
        if (more) {
            const float* s = (scol < 256) ? (g_fc1a_t + (k0 + 16 + srow) * 256 + scol)
                                          : (g_fc1b_t + (k0 + 16 + srow) * 256 + (scol - 256));
#pragma unroll
            for (int u = 0; u < 8; u++) nv[u] = *(const float4*)(s + u * 4);
        }
        const float* Wb = sW + buf * WBUF;
#pragma unroll
        for (int ks = 0; ks < 8; ks += 8) {  // two k8 subtiles handled below
#pragma unroll
            for (int half = 0; half < 2; half++) {
                const int kk = k0 + half * 8;
                const float* Pr = P + (wr * 16 + g) * XLD + kk + tig;
                const float* Qr = Q + (wr * 16 + g) * XLD + kk + tig;
                unsigned pa0 = fbits(Pr[0]), pa1 = fbits(Pr[8 * XLD]);
                unsigned pa2 = fbits(Pr[4]), pa3 = fbits(Pr[8 * XLD + 4]);
                unsigned qa0 = fbits(Qr[0]), qa1 = fbits(Qr[8 * XLD]);
                unsigned qa2 = fbits(Qr[4]), qa3 = fbits(Qr[8 * XLD + 4]);
                const float* Bp = Wb + (half * 8 + tig) * FW_LD + wc * 128 + g;
                const float* Bq = Bp + 256;
#pragma unroll
                for (int nt = 0; nt < 16; nt++) {
                    unsigned b0 = fbits(Bp[nt * 8]);
                    unsigned b1 = fbits(Bp[nt * 8 + 4 * FW_LD]);
                    mma_tf32(acc[nt], pa0, pa1, pa2, pa3, b0, b1);
                    unsigned c0 = fbits(Bq[nt * 8]);
                    unsigned c1 = fbits(Bq[nt * 8 + 4 * FW_LD]);
                    mma_tf32(acc[nt], qa0, qa1, qa2, qa3, c0, c1);
                }
            }
        }
        if (more) {
            float* d = sW + (buf ^ 1) * WBUF + srow * FW_LD + scol;
#pragma unroll
            for (int u = 0; u < 8; u++) *(float4*)(d + u * 4) = nv[u];
        }
        buf ^= 1;
        __syncthreads();
    }

    // spill acc to scr, then relu+bias+fc2 reduction
#pragma unroll
    for (int nt = 0; nt < 16; nt++) {
        const int c0 = wc * 128 + nt * 8 + 2 * tig;
        const int r = wr * 16 + g;
        *(float2*)(scr + r * XLD + c0)       = make_float2(acc[nt][0], acc[nt][1]);
        *(float2*)(scr + (r + 8) * XLD + c0) = make_float2(acc[nt][2], acc[nt][3]);
    }
    __syncthreads();

    const int row = tid >> 2, q = tid & 3;
    float s = 0.f;
    const float* rp = scr + row * XLD;
#pragma unroll 8
    for (int j = q * 64; j < q * 64 + 64; j++) {
        float h = fmaxf(rp[j] + sFb[j], 0.f);
        s = fmaf(h, sFc2[j], s);
    }
    s += __shfl_xor_sync(0xffffffffu, s, 1);
    s += __shfl_xor_sync(0xffffffffu, s, 2);
    if (q == 0) out[b * 256 + r0 + row] = s + fc2b0;
}

#define SMEM_FLOATS (2 * TM * XLD + 2 * WBUF + 4 * 256 + 2 * 64)
#define SMEM_BYTES  (SMEM_FLOATS * 4)

__global__ __launch_bounds__(256, 1)
void fused_chain(const float* __restrict__ fc1_b, const float* __restrict__ fc2_w,
                 const float* __restrict__ fc2_b, float* __restrict__ out) {
    extern __shared__ float sm[];
    float* P     = sm;                 // [TM][XLD]
    float* Q     = P + TM * XLD;       // [TM][XLD]
    float* sW    = Q + TM * XLD;       // 2 x WBUF
    float* sAffA = sW + 2 * WBUF;
    float* sAffV = sAffA + 256;
    float* sFc2  = sAffV + 256;
    float* sFb   = sFc2 + 256;
    float* sE1   = sFb + 256;
    float* sE2   = sE1 + 64;

    const int tid = threadIdx.x;
    const int b   = blockIdx.y;
    const int r0  = blockIdx.x * TM;
    const float scale = 0.0625f;   // 1/sqrt(256)

    sAffA[tid] = g_aff_a[b * 256 + tid];
    sAffV[tid] = g_aff_v[b * 256 + tid];
    sFc2[tid]  = fc2_w[tid];
    sFb[tid]   = fc1_b[tid];
    if (tid < TM) {
        sE1[tid] = g_enc1[b * 256 + r0 + tid];
        sE2[tid] = g_enc2[b * 256 + r0 + tid];
    }
    const float fc2b0 = fc2_b[0];
    __syncthreads();

    // attn_a tile -> P  (tf32-rounded)
    for (int idx = tid; idx < TM * 256; idx += 256) {
        int i = idx >> 8, m = idx & 255;
        P[i * XLD + m] = tf32r(tanhf(sE1[i] * sAffA[m] * scale));
    }
    __syncthreads();

    // H_a = relu(attn_a @ wca^T + A1[i,:])  -> Q
    tile_gemm_mma(P, g_wca_t, sW, Q, g_A1 + r0 * 256, true, tid);
    // ae1 = H_a @ wha^T + enc1[i,:]         -> P
    tile_gemm_mma(Q, g_wha_t, sW, P, g_enc1 + r0 * 256, false, tid);

    // attn_v tile -> Q
    for (int idx = tid; idx < TM * 256; idx += 256) {
        int i = idx >> 8, m = idx & 255;
        Q[i * XLD + m] = tf32r(tanhf(sE2[i] * sAffV[m] * scale));
    }
    __syncthreads();

    // H_v = relu(attn_v @ wcv^T + A2[i,:])  -> Q (in place)
    tile_gemm_mma(Q, g_wcv_t, sW, Q, g_A2 + r0 * 256, true, tid);
    // ae2 = H_v @ whv^T + enc2[i,:]         -> Q (in place)
    tile_gemm_mma(Q, g_whv_t, sW, Q, g_enc2 + r0 * 256, false, tid);

    // fc1 (both halves) + relu + fc2 reduction -> out
    fc_final_mma(P, Q, sW, P /*scratch*/, sFb, sFc2, fc2b0, out, b, r0, tid);
}

// ---------------- launch --------------------------------------------------
extern "C" void kernel_launch(void* const* d_in, const int* in_sizes, int n_in,
                              void* d_out, int out_size) {
    const float* features1 = (const float*)d_in[0];
    const float* features2 = (const float*)d_in[1];
    const float* enc1_w = (const float*)d_in[2];
    const float* enc1_b = (const float*)d_in[3];
    const float* enc2_w = (const float*)d_in[4];
    const float* enc2_b = (const float*)d_in[5];
    const float* affa_w = (const float*)d_in[6];
    const float* affv_w = (const float*)d_in[7];
    const float* wa_w   = (const float*)d_in[8];
    const float* wv_w   = (const float*)d_in[9];
    const float* wca_w  = (const float*)d_in[10];
    const float* wcv_w  = (const float*)d_in[11];
    const float* wha_w  = (const float*)d_in[12];
    const float* whv_w  = (const float*)d_in[13];
    const float* fc1_w  = (const float*)d_in[14];
    const float* fc1_b  = (const float*)d_in[15];
    const float* fc2_w  = (const float*)d_in[16];
    const float* fc2_b  = (const float*)d_in[17];
    float* out = (float*)d_out;

    cudaFuncSetAttribute(fused_chain, cudaFuncAttributeMaxDynamicSharedMemorySize,
                         SMEM_BYTES);

    transpose_prep<<<dim3(8, 8, 6), dim3(32, 32)>>>(wca_w, wcv_w, wha_w, whv_w, fc1_w);

    enc_gemms<<<dim3(16, 16, 2), dim3(16, 16)>>>(features1, features2,
                                                 enc1_w, enc1_b, enc2_w, enc2_b);
    quad_gemms<<<dim3(16, 16, 4), dim3(16, 16)>>>(affa_w, affv_w, wa_w, wv_w);

    fused_chain<<<dim3(256 / TM, 256), 256, SMEM_BYTES>>>(fc1_b, fc2_w, fc2_b, out);
}

// round 14
// speedup vs baseline: 4.7456x; 3.0045x over previous
#include <cuda_runtime.h>
#include <cuda_fp16.h>
#include <math.h>

#define EDIM 256
#define TM 64
#define XW 132      // u32 words per P/Q row (264 halves); 132%32=4 -> banks 4g+t, conflict-free
#define BW 264      // u32 words per B kp-row; 264%32=8 -> banks 8t+g, conflict-free
#define BCH (16*BW) // words per B chunk buffer

typedef unsigned int u32;

// ---------------- device-global scratch (allocation-free workaround) --------
__device__ float g_enc1[EDIM*EDIM], g_enc2[EDIM*EDIM];
__device__ float g_aff_a[EDIM*EDIM], g_aff_v[EDIM*EDIM];
__device__ float g_A1[EDIM*EDIM],  g_A2[EDIM*EDIM];
// fp16 pair-interleaved weights: g_wp[z][kp*256 + n] = half2{W[n][2kp], W[n][2kp+1]}
// z: 0=wca 1=wha 2=wcv 3=whv 4=fc1a 5=fc1b
__device__ u32 g_wp[6][128*256];

// ---------------- fp16 tensor-core mma (m16n8k16, fp32 accum) ---------------
__device__ __forceinline__ void hmma(float* c, u32 a0, u32 a1, u32 a2, u32 a3,
                                     u32 b0, u32 b1) {
    asm("mma.sync.aligned.m16n8k16.row.col.f32.f16.f16.f32 "
        "{%0,%1,%2,%3}, {%4,%5,%6,%7}, {%8,%9}, {%0,%1,%2,%3};"
        : "+f"(c[0]), "+f"(c[1]), "+f"(c[2]), "+f"(c[3])
        : "r"(a0), "r"(a1), "r"(a2), "r"(a3), "r"(b0), "r"(b1));
}
__device__ __forceinline__ u32 packh2(float x, float y) {
    __half2 h = __floats2half2_rn(x, y);
    return *(u32*)&h;
}

// ---------------- prologue GEMM body: C = A @ B^T (+bias), scalar (KNOWN GOOD)
__device__ __forceinline__ void gemm_body_s(const float* __restrict__ A,
                                            const float* __restrict__ B,
                                            const float* __restrict__ bias,
                                            float* __restrict__ C, int K) {
    __shared__ float As[16][17], Bs[16][17];
    int tx = threadIdx.x, ty = threadIdx.y;
    int row = blockIdx.y * 16 + ty;
    int col = blockIdx.x * 16 + tx;
    float acc = 0.f;
    for (int k0 = 0; k0 < K; k0 += 16) {
        As[ty][tx] = A[row * K + k0 + tx];
        Bs[ty][tx] = B[(blockIdx.x * 16 + ty) * K + k0 + tx];
        __syncthreads();
#pragma unroll
        for (int kk = 0; kk < 16; kk++) acc = fmaf(As[ty][kk], Bs[tx][kk], acc);
        __syncthreads();
    }
    C[row * 256 + col] = acc + (bias ? bias[col] : 0.f);
}

__global__ void enc_gemms(const float* __restrict__ f1, const float* __restrict__ f2,
                          const float* __restrict__ w1, const float* __restrict__ b1,
                          const float* __restrict__ w2, const float* __restrict__ b2) {
    if (blockIdx.z == 0) gemm_body_s(f1, w1, b1, g_enc1, 768);
    else                 gemm_body_s(f2, w2, b2, g_enc2, 768);
}
__global__ void quad_gemms(const float* __restrict__ affa, const float* __restrict__ affv,
                           const float* __restrict__ wa,   const float* __restrict__ wv) {
    switch (blockIdx.z) {
        case 0: gemm_body_s(g_enc1, affa, nullptr, g_aff_a, 256); break;
        case 1: gemm_body_s(g_enc2, affv, nullptr, g_aff_v, 256); break;
        case 2: gemm_body_s(g_enc1, wa,   nullptr, g_A1,    256); break;
        default: gemm_body_s(g_enc2, wv,  nullptr, g_A2,    256); break;
    }
}

// pack weights to fp16 pair-interleaved k-major layout
__global__ void pack_weights(const float* __restrict__ wca, const float* __restrict__ wha,
                             const float* __restrict__ wcv, const float* __restrict__ whv,
                             const float* __restrict__ fc1) {
    int z = blockIdx.z;
    const float* src; int ldk, co;
    switch (z) {
        case 0: src = wca; ldk = 256; co = 0;   break;
        case 1: src = wha; ldk = 256; co = 0;   break;
        case 2: src = wcv; ldk = 256; co = 0;   break;
        case 3: src = whv; ldk = 256; co = 0;   break;
        case 4: src = fc1; ldk = 512; co = 0;   break;
        default: src = fc1; ldk = 512; co = 256; break;
    }
    int kp = blockIdx.y;            // 0..127
    int n  = threadIdx.x;           // 0..255
    float2 w = *(const float2*)&src[n * ldk + co + 2 * kp];
    g_wp[z][kp * 256 + n] = packh2(w.x, w.y);
}

// ---------------- fused chain: fp16 mma, 8 warps (2 row x 4 col, 32x64/warp) -
// One GEMM pass: acc[16][4] += A(64x256 fp16 in smem) @ W^T (streamed fp16).
// Double buffer, ONE barrier per 32-k chunk (discipline proven in R9/R11).
__device__ __forceinline__ void run_pass(const u32* __restrict__ gw,
                                         u32* __restrict__ sB,
                                         const u32* __restrict__ Aw,
                                         float (*acc)[4], int tid) {
    const int lane = tid & 31, wid = tid >> 5;
    const int wr = wid & 1, wc = wid >> 1;
    const int g = lane >> 2, t = lane & 3;
    const int mr = wr * 32, nc = wc * 64;

    // stage chunk 0 (kp rows 0..15)
#pragma unroll
    for (int kpl = 0; kpl < 16; kpl++) sB[kpl * BW + tid] = gw[kpl * 256 + tid];
    __syncthreads();

#pragma unroll 1
    for (int c = 0; c < 8; c++) {
        u32 v[16];
        const bool more = c < 7;
        if (more) {
#pragma unroll
            for (int kpl = 0; kpl < 16; kpl++)
                v[kpl] = gw[((c + 1) * 16 + kpl) * 256 + tid];
        }
        const u32* Bb = sB + (c & 1) * BCH;
#pragma unroll
        for (int s = 0; s < 2; s++) {
            const int kw = c * 16 + s * 8;       // word offset into A row
            u32 a[2][4];
#pragma unroll
            for (int mt = 0; mt < 2; mt++) {
                const u32* Ar = Aw + (mr + mt * 16 + g) * XW + kw + t;
                a[mt][0] = Ar[0];
                a[mt][1] = Ar[8 * XW];
                a[mt][2] = Ar[4];
                a[mt][3] = Ar[8 * XW + 4];
            }
#pragma unroll
            for (int nt = 0; nt < 8; nt++) {
                const int n = nc + nt * 8 + g;
                u32 b0 = Bb[(s * 8 + t) * BW + n];
                u32 b1 = Bb[(s * 8 + 4 + t) * BW + n];
                hmma(acc[nt],     a[0][0], a[0][1], a[0][2], a[0][3], b0, b1);
                hmma(acc[8 + nt], a[1][0], a[1][1], a[1][2], a[1][3], b0, b1);
            }
        }
        if (more) {
            u32* d = sB + ((c + 1) & 1) * BCH;
#pragma unroll
            for (int kpl = 0; kpl < 16; kpl++) d[kpl * BW + tid] = v[kpl];
        }
        __syncthreads();
    }
}

// epilogue: dst[r][j] = act(acc + gAdd[r*256+j]) as fp16 into smem (word layout XW)
__device__ __forceinline__ void epi_store(float (*acc)[4], const float* __restrict__ gAdd,
                                          u32* __restrict__ dstw, bool do_relu, int tid) {
    const int lane = tid & 31, wid = tid >> 5;
    const int wr = wid & 1, wc = wid >> 1;
    const int g = lane >> 2, t = lane & 3;
    const int mr = wr * 32, nc = wc * 64;
#pragma unroll
    for (int mt = 0; mt < 2; mt++)
#pragma unroll
        for (int nt = 0; nt < 8; nt++) {
            const int j0 = nc + nt * 8 + 2 * t;
            const int r1 = mr + mt * 16 + g;
            float* a = acc[mt * 8 + nt];
            float2 g0 = *(const float2*)&gAdd[r1 * 256 + j0];
            float2 g1 = *(const float2*)&gAdd[(r1 + 8) * 256 + j0];
            float v0 = a[0] + g0.x, v1 = a[1] + g0.y;
            float v2 = a[2] + g1.x, v3 = a[3] + g1.y;
            if (do_relu) {
                v0 = fmaxf(v0, 0.f); v1 = fmaxf(v1, 0.f);
                v2 = fmaxf(v2, 0.f); v3 = fmaxf(v3, 0.f);
            }
            const int cw = (nc >> 1) + nt * 4 + t;
            dstw[r1 * XW + cw]       = packh2(v0, v1);
            dstw[(r1 + 8) * XW + cw] = packh2(v2, v3);
        }
    __syncthreads();
}

#define SMEM_WORDS (3 * 8448 + 5 * 256 + 2 * 64)
#define SMEM_BYTES (SMEM_WORDS * 4)

__global__ __launch_bounds__(256, 1)
void fused_hmma(const float* __restrict__ fc1_b, const float* __restrict__ fc2_w,
                const float* __restrict__ fc2_b, float* __restrict__ out) {
    extern __shared__ u32 usm[];
    u32* uP   = usm;                    // [64][XW]
    u32* uQ   = uP + 8448;              // [64][XW]
    u32* uB   = uQ + 8448;              // 2 x [16][BW]
    float* fAffA = (float*)(uB + 8448);
    float* fAffV = fAffA + 256;
    float* fFb   = fAffV + 256;
    float* fF2   = fFb + 256;
    float* fRed  = fF2 + 256;           // [4][64]
    float* fE1   = fRed + 256;
    float* fE2   = fE1 + 64;

    const int tid = threadIdx.x;
    const int b   = blockIdx.y;
    const int r0  = blockIdx.x * TM;
    const float scale = 0.0625f;        // 1/sqrt(256)

    fAffA[tid] = g_aff_a[b * 256 + tid];
    fAffV[tid] = g_aff_v[b * 256 + tid];
    fFb[tid]   = fc1_b[tid];
    fF2[tid]   = fc2_w[tid];
    if (tid < TM) {
        fE1[tid] = g_enc1[b * 256 + r0 + tid];
        fE2[tid] = g_enc2[b * 256 + r0 + tid];
    }
    const float fc2b0 = fc2_b[0];
    __syncthreads();

    float acc[16][4];

    // ---- attn_a -> P (fp16) ----
    for (int idx = tid; idx < TM * 128; idx += 256) {
        int i = idx >> 7, jp = idx & 127;
        float ev = fE1[i];
        uP[i * XW + jp] = packh2(tanhf(ev * fAffA[2 * jp] * scale),
                                 tanhf(ev * fAffA[2 * jp + 1] * scale));
    }
    __syncthreads();

    // ---- GEMM1: H_a = relu(attn_a @ wca^T + A1) -> Q ----
#pragma unroll
    for (int i = 0; i < 16; i++)
#pragma unroll
        for (int e = 0; e < 4; e++) acc[i][e] = 0.f;
    run_pass(g_wp[0], uB, uP, acc, tid);
    epi_store(acc, g_A1 + r0 * 256, uQ, true, tid);

    // ---- GEMM2: ae1 = H_a @ wha^T + enc1 -> P ----
#pragma unroll
    for (int i = 0; i < 16; i++)
#pragma unroll
        for (int e = 0; e < 4; e++) acc[i][e] = 0.f;
    run_pass(g_wp[1], uB, uQ, acc, tid);
    epi_store(acc, g_enc1 + r0 * 256, uP, false, tid);

    // ---- attn_v -> Q ----
    for (int idx = tid; idx < TM * 128; idx += 256) {
        int i = idx >> 7, jp = idx & 127;
        float ev = fE2[i];
        uQ[i * XW + jp] = packh2(tanhf(ev * fAffV[2 * jp] * scale),
                                 tanhf(ev * fAffV[2 * jp + 1] * scale));
    }
    __syncthreads();

    // ---- GEMM3: H_v = relu(attn_v @ wcv^T + A2) -> Q (in place) ----
#pragma unroll
    for (int i = 0; i < 16; i++)
#pragma unroll
        for (int e = 0; e < 4; e++) acc[i][e] = 0.f;
    run_pass(g_wp[2], uB, uQ, acc, tid);
    epi_store(acc, g_A2 + r0 * 256, uQ, true, tid);

    // ---- GEMM4: ae2 = H_v @ whv^T + enc2 -> Q (in place) ----
#pragma unroll
    for (int i = 0; i < 16; i++)
#pragma unroll
        for (int e = 0; e < 4; e++) acc[i][e] = 0.f;
    run_pass(g_wp[3], uB, uQ, acc, tid);
    epi_store(acc, g_enc2 + r0 * 256, uQ, false, tid);

    // ---- fc1: h = relu(ae1 @ fc1a^T + ae2 @ fc1b^T + b1) ----
#pragma unroll
    for (int i = 0; i < 16; i++)
#pragma unroll
        for (int e = 0; e < 4; e++) acc[i][e] = 0.f;
    run_pass(g_wp[4], uB, uP, acc, tid);
    run_pass(g_wp[5], uB, uQ, acc, tid);

    // ---- final: out = relu(h)· fc2 + b2 ----
    {
        const int lane = tid & 31, wid = tid >> 5;
        const int wr = wid & 1, wc = wid >> 1;
        const int g = lane >> 2, t = lane & 3;
        const int mr = wr * 32, nc = wc * 64;
        float rp[4] = {0.f, 0.f, 0.f, 0.f};
#pragma unroll
        for (int mt = 0; mt < 2; mt++)
#pragma unroll
            for (int nt = 0; nt < 8; nt++) {
                const int j0 = nc + nt * 8 + 2 * t;
                float* a = acc[mt * 8 + nt];
                float fb0 = fFb[j0], fb1 = fFb[j0 + 1];
                float f20 = fF2[j0], f21 = fF2[j0 + 1];
                rp[mt * 2]     += fmaxf(a[0] + fb0, 0.f) * f20 + fmaxf(a[1] + fb1, 0.f) * f21;
                rp[mt * 2 + 1] += fmaxf(a[2] + fb0, 0.f) * f20 + fmaxf(a[3] + fb1, 0.f) * f21;
            }
#pragma unroll
        for (int r = 0; r < 4; r++) {
            rp[r] += __shfl_xor_sync(0xffffffffu, rp[r], 1);
            rp[r] += __shfl_xor_sync(0xffffffffu, rp[r], 2);
        }
        if (t == 0) {
#pragma unroll
            for (int mt = 0; mt < 2; mt++) {
                fRed[wc * 64 + mr + mt * 16 + g]     = rp[mt * 2];
                fRed[wc * 64 + mr + mt * 16 + g + 8] = rp[mt * 2 + 1];
            }
        }
    }
    __syncthreads();
    if (tid < TM) {
        out[b * 256 + r0 + tid] = fRed[tid] + fRed[64 + tid] + fRed[128 + tid]
                                + fRed[192 + tid] + fc2b0;
    }
}

// ---------------- launch --------------------------------------------------
extern "C" void kernel_launch(void* const* d_in, const int* in_sizes, int n_in,
                              void* d_out, int out_size) {
    const float* features1 = (const float*)d_in[0];
    const float* features2 = (const float*)d_in[1];
    const float* enc1_w = (const float*)d_in[2];
    const float* enc1_b = (const float*)d_in[3];
    const float* enc2_w = (const float*)d_in[4];
    const float* enc2_b = (const float*)d_in[5];
    const float* affa_w = (const float*)d_in[6];
    const float* affv_w = (const float*)d_in[7];
    const float* wa_w   = (const float*)d_in[8];
    const float* wv_w   = (const float*)d_in[9];
    const float* wca_w  = (const float*)d_in[10];
    const float* wcv_w  = (const float*)d_in[11];
    const float* wha_w  = (const float*)d_in[12];
    const float* whv_w  = (const float*)d_in[13];
    const float* fc1_w  = (const float*)d_in[14];
    const float* fc1_b  = (const float*)d_in[15];
    const float* fc2_w  = (const float*)d_in[16];
    const float* fc2_b  = (const float*)d_in[17];
    float* out = (float*)d_out;

    cudaFuncSetAttribute(fused_hmma, cudaFuncAttributeMaxDynamicSharedMemorySize,
                         SMEM_BYTES);

    pack_weights<<<dim3(1, 128, 6), 256>>>(wca_w, wha_w, wcv_w, whv_w, fc1_w);
    enc_gemms<<<dim3(16, 16, 2), dim3(16, 16)>>>(features1, features2,
                                                 enc1_w, enc1_b, enc2_w, enc2_b);
    quad_gemms<<<dim3(16, 16, 4), dim3(16, 16)>>>(affa_w, affv_w, wa_w, wv_w);

    fused_hmma<<<dim3(256 / TM, 256), 256, SMEM_BYTES>>>(fc1_b, fc2_w, fc2_b, out);
}